// round 7
// baseline (speedup 1.0000x reference)
#include <cuda_runtime.h>

// Shapes: x, y : (16, 64, 256, 256) fp32 ; out : (16, 256, 256) fp32
// out[b,i] = sum_c x[b,c,i] * w[b,c],  w[b,c] = sum_j y[b,c,j] / (65536*4194304)
//
// Fused single kernel, 1024 blocks x 256 threads, all resident in one wave
// (launch_bounds(256,7) -> 7 blocks/SM x 148 SMs = 1036 >= 1024 : required,
// the per-batch barrier deadlocks if any block of a batch is non-resident).
//
// Barrier: monotonic per-batch ticket counter (NEVER reset). ticket/64 gives
// the round; wait until counter >= (round+1)*64. Single location, total order
// from atomicAdd, stale reads only under-read -> deadlock-free by construction.
//
// Phase B: branch-free uniform 64-plane sweep (w[own_c] zeroed; own plane's
// term pre-accumulated between barrier arrive and wait to keep DRAM busy).
// R7 micro: __stcs output store, additive pointer stepping, .cs everywhere.

#define NB 16
#define NC 64
#define HW 65536               // 256*256
#define HW4 (HW / 4)           // 16384 float4 per (b,c) plane
#define SCALE (1.0f / (65536.0f * 4194304.0f))  // exact: 2^-38

__device__ float g_w[NB * NC];
__device__ unsigned int g_cnt[NB];     // monotonic ticket counter (never reset)

__global__ void __launch_bounds__(256, 7)
fused_kernel(const float4* __restrict__ x4,
             const float4* __restrict__ y4,
             float4* __restrict__ out4) {
    const int blk = blockIdx.x;            // 0..1023 == plane index b*64+c
    const int b = blk >> 6;                // batch
    const int own_c = blk & 63;            // this block's channel / output chunk
    const int t = threadIdx.x;

    __shared__ float w[NC];
    __shared__ float red[8];
    __shared__ unsigned int s_target;

    // ---------------- Phase A: reduce y-plane blk ----------------
    {
        const float4* p = y4 + (size_t)blk * HW4 + t;
        float s = 0.0f;
        #pragma unroll 8
        for (int k = 0; k < 64; ++k) {
            float4 v = __ldcs(p);             // y read exactly once: stream
            p += 256;
            s += (v.x + v.y) + (v.z + v.w);
        }
        #pragma unroll
        for (int o = 16; o > 0; o >>= 1)
            s += __shfl_xor_sync(0xFFFFFFFF, s, o);
        if ((t & 31) == 0) red[t >> 5] = s;
    }
    __syncthreads();

    // ------------- Publish w_own + barrier ARRIVE (ticket, no wait) --------
    if (t == 0) {
        float tot = 0.0f;
        #pragma unroll
        for (int i = 0; i < 8; ++i) tot += red[i];
        const float wo = tot * SCALE;
        g_w[blk] = wo;                                // publish for batch peers
        red[0] = wo;                                  // local broadcast slot
        __threadfence();                              // release g_w[blk]
        unsigned ticket = atomicAdd(&g_cnt[b], 1u);   // totally ordered arrive
        s_target = ((ticket >> 6) + 1u) << 6;         // end of this round
    }
    __syncthreads();
    const float w_own = red[0];

    // ------- Phase B part 1: own plane pre-accumulation (overlaps wait) ----
    const float4* pxb = x4 + (size_t)b * NC * HW4 + own_c * 256 + t;
    float4 acc;
    {
        float4 v = __ldcs(pxb + (size_t)own_c * HW4);
        acc.x = v.x * w_own;
        acc.y = v.y * w_own;
        acc.z = v.z * w_own;
        acc.w = v.w * w_own;
    }

    // ---------------- Barrier WAIT (overlapped by the loads above) ---------
    if (t == 0) {
        const unsigned target = s_target;
        while (*(volatile unsigned*)&g_cnt[b] < target)
            __nanosleep(64);
        __threadfence();                              // acquire before g_w reads
    }
    __syncthreads();
    // Reload all weights; ZERO the own channel (already accumulated) so the
    // main loop is uniform and branch-free.
    if (t < NC) w[t] = (t == own_c) ? 0.0f : __ldcg(&g_w[b * NC + t]);
    __syncthreads();

    // ------- Phase B part 2: uniform branch-free 64-plane sweep ------------
    {
        const float4* p = pxb;
        #pragma unroll 8
        for (int c = 0; c < NC; ++c) {
            float4 v = __ldcs(p);                     // x read exactly once
            p += HW4;                                 // additive stepping
            const float wc = w[c];
            acc.x += v.x * wc;
            acc.y += v.y * wc;
            acc.z += v.z * wc;
            acc.w += v.w * wc;
        }
    }

    __stcs(&out4[(size_t)blk * 256 + t], acc);        // streaming store

extern_c_marker: ;
}

extern "C" void kernel_launch(void* const* d_in, const int* in_sizes, int n_in,
                              void* d_out, int out_size) {
    const float4* x4 = (const float4*)d_in[0];
    const float4* y4 = (const float4*)d_in[1];
    float4* out4 = (float4*)d_out;

    fused_kernel<<<NB * NC, 256>>>(x4, y4, out4);
}

// round 8
// speedup vs baseline: 1.0090x; 1.0090x over previous
#include <cuda_runtime.h>

// Shapes: x, y : (16, 64, 256, 256) fp32 ; out : (16, 256, 256) fp32
// out[b,i] = sum_c x[b,c,i] * w[b,c],  w[b,c] = sum_j y[b,c,j] / (65536*4194304)
//
// Fused single kernel, 1024 blocks x 256 threads, all resident in one wave
// (launch_bounds(256,7) -> 7 blocks/SM x 148 SMs = 1036 >= 1024 : required,
// the per-batch barrier deadlocks if any block of a batch is non-resident).
//
// Barrier: monotonic per-batch ticket counter (NEVER reset). ticket/64 gives
// the round; wait until counter >= (round+1)*64. Single location, total order
// from atomicAdd, stale reads only under-read -> deadlock-free by construction.
//
// Phase B is a BRANCH-FREE uniform 64-iteration INDEXED loop (indexed
// addressing is load-bearing: independent per-load address IMADs let ptxas
// front-batch the LDG.128s; additive pointer stepping measurably regressed).
// w[own_c] zeroed after the barrier; own plane's term was pre-accumulated
// between barrier-arrive and barrier-wait, keeping DRAM busy while phase-A
// stragglers finish.
//
// Best measured: kernel 80.5us, 6.71 TB/s (~96% of the 77.5us streaming
// floor at this chip's achieved 6.7 TB/s LTS ceiling).

#define NB 16
#define NC 64
#define HW 65536               // 256*256
#define HW4 (HW / 4)           // 16384 float4 per (b,c) plane
#define SCALE (1.0f / (65536.0f * 4194304.0f))  // exact: 2^-38

__device__ float g_w[NB * NC];
__device__ unsigned int g_cnt[NB];     // monotonic ticket counter (never reset)

__global__ void __launch_bounds__(256, 7)
fused_kernel(const float4* __restrict__ x4,
             const float4* __restrict__ y4,
             float4* __restrict__ out4) {
    const int blk = blockIdx.x;            // 0..1023 == plane index b*64+c
    const int b = blk >> 6;                // batch
    const int own_c = blk & 63;            // this block's channel / output chunk
    const int t = threadIdx.x;

    __shared__ float w[NC];
    __shared__ float red[8];
    __shared__ unsigned int s_target;

    // ---------------- Phase A: reduce y-plane blk ----------------
    {
        const float4* p = y4 + (size_t)blk * HW4;
        float s = 0.0f;
        #pragma unroll 8
        for (int k = 0; k < 64; ++k) {
            float4 v = __ldcs(&p[t + k * 256]);   // y read exactly once: stream
            s += (v.x + v.y) + (v.z + v.w);
        }
        #pragma unroll
        for (int o = 16; o > 0; o >>= 1)
            s += __shfl_xor_sync(0xFFFFFFFF, s, o);
        if ((t & 31) == 0) red[t >> 5] = s;
    }
    __syncthreads();

    // ------------- Publish w_own + barrier ARRIVE (ticket, no wait) --------
    float w_own = 0.0f;
    if (t == 0) {
        float tot = 0.0f;
        #pragma unroll
        for (int i = 0; i < 8; ++i) tot += red[i];
        const float wo = tot * SCALE;
        g_w[blk] = wo;                                // publish for batch peers
        red[0] = wo;                                  // local broadcast slot
        __threadfence();                              // release g_w[blk]
        unsigned ticket = atomicAdd(&g_cnt[b], 1u);   // totally ordered arrive
        s_target = ((ticket >> 6) + 1u) << 6;         // end of this round
    }
    __syncthreads();
    w_own = red[0];

    // ------- Phase B part 1: own plane pre-accumulation (overlaps wait) ----
    const float4* pxb = x4 + (size_t)b * NC * HW4 + own_c * 256 + t;
    float4 acc;
    {
        float4 v = __ldcg(pxb + (size_t)own_c * HW4); // .cg: will be re-read below
        acc.x = v.x * w_own;
        acc.y = v.y * w_own;
        acc.z = v.z * w_own;
        acc.w = v.w * w_own;
    }

    // ---------------- Barrier WAIT (overlapped by the loads above) ---------
    if (t == 0) {
        const unsigned target = s_target;
        while (*(volatile unsigned*)&g_cnt[b] < target)
            __nanosleep(64);
        __threadfence();                              // acquire before g_w reads
    }
    __syncthreads();
    // Reload all weights; ZERO the own channel (already accumulated) so the
    // main loop is uniform and branch-free.
    if (t < NC) w[t] = (t == own_c) ? 0.0f : __ldcg(&g_w[b * NC + t]);
    __syncthreads();

    // ------- Phase B part 2: uniform branch-free 64-plane sweep ------------
    #pragma unroll 8
    for (int c = 0; c < NC; ++c) {
        float4 v = __ldcs(pxb + (size_t)c * HW4);
        const float wc = w[c];
        acc.x += v.x * wc;
        acc.y += v.y * wc;
        acc.z += v.z * wc;
        acc.w += v.w * wc;
    }

    out4[(size_t)blk * 256 + t] = acc;
}

extern "C" void kernel_launch(void* const* d_in, const int* in_sizes, int n_in,
                              void* d_out, int out_size) {
    const float4* x4 = (const float4*)d_in[0];
    const float4* y4 = (const float4*)d_in[1];
    float4* out4 = (float4*)d_out;

    fused_kernel<<<NB * NC, 256>>>(x4, y4, out4);
}

// round 9
// speedup vs baseline: 1.0101x; 1.0012x over previous
#include <cuda_runtime.h>

// Shapes: x, y : (16, 64, 256, 256) fp32 ; out : (16, 256, 256) fp32
// out[b,i] = sum_c x[b,c,i] * w[b,c],  w[b,c] = sum_j y[b,c,j] / (65536*4194304)
//
// FINAL. Fused single kernel, 1024 blocks x 256 threads, all resident in one
// wave (launch_bounds(256,7) -> 7 x 148 = 1036 >= 1024 : required, the
// per-batch barrier deadlocks if any block of a batch is non-resident).
//
// Barrier: monotonic per-batch ticket counter (NEVER reset). ticket/64 gives
// the round; wait until counter >= (round+1)*64. Single location, total order
// from atomicAdd, stale reads only under-read -> deadlock-free by construction.
// Counter value differs across graph replays but output does not.
//
// Validated-by-measurement design points:
//  - fusion vs two kernels:            ~ +1.0 us (launch gap + tail drain)
//  - own-plane pre-accumulation between barrier arrive and wait: ~ +0.6 us
//  - branch-free indexed 64-plane sweep (w[own_c]=0): ~ +0.6 us
//  - grid=256 "long burst" variant:    -16 us   (occupancy/MLP collapse)
//  - additive pointer stepping:        -1.5 us  (serializes address chain,
//    kills LDG front-batching) — indexed addressing is load-bearing.
//
// Best measured: kernel 80.5us @ 6.71 TB/s = ~96% of the 77.5us streaming
// floor at this chip's achieved ~6.7 TB/s LTS ceiling (path-independent cap;
// remaining gap is ramp + barrier transition + tail, all below run noise).

#define NB 16
#define NC 64
#define HW 65536               // 256*256
#define HW4 (HW / 4)           // 16384 float4 per (b,c) plane
#define SCALE (1.0f / (65536.0f * 4194304.0f))  // exact: 2^-38

__device__ float g_w[NB * NC];
__device__ unsigned int g_cnt[NB];     // monotonic ticket counter (never reset)

__global__ void __launch_bounds__(256, 7)
fused_kernel(const float4* __restrict__ x4,
             const float4* __restrict__ y4,
             float4* __restrict__ out4) {
    const int blk = blockIdx.x;            // 0..1023 == plane index b*64+c
    const int b = blk >> 6;                // batch
    const int own_c = blk & 63;            // this block's channel / output chunk
    const int t = threadIdx.x;

    __shared__ float w[NC];
    __shared__ float red[8];
    __shared__ unsigned int s_target;

    // ---------------- Phase A: reduce y-plane blk ----------------
    {
        const float4* p = y4 + (size_t)blk * HW4;
        float s = 0.0f;
        #pragma unroll 8
        for (int k = 0; k < 64; ++k) {
            float4 v = __ldcs(&p[t + k * 256]);   // y read exactly once: stream
            s += (v.x + v.y) + (v.z + v.w);
        }
        #pragma unroll
        for (int o = 16; o > 0; o >>= 1)
            s += __shfl_xor_sync(0xFFFFFFFF, s, o);
        if ((t & 31) == 0) red[t >> 5] = s;
    }
    __syncthreads();

    // ------------- Publish w_own + barrier ARRIVE (ticket, no wait) --------
    float w_own = 0.0f;
    if (t == 0) {
        float tot = 0.0f;
        #pragma unroll
        for (int i = 0; i < 8; ++i) tot += red[i];
        const float wo = tot * SCALE;
        g_w[blk] = wo;                                // publish for batch peers
        red[0] = wo;                                  // local broadcast slot
        __threadfence();                              // release g_w[blk]
        unsigned ticket = atomicAdd(&g_cnt[b], 1u);   // totally ordered arrive
        s_target = ((ticket >> 6) + 1u) << 6;         // end of this round
    }
    __syncthreads();
    w_own = red[0];

    // ------- Phase B part 1: own plane pre-accumulation (overlaps wait) ----
    const float4* pxb = x4 + (size_t)b * NC * HW4 + own_c * 256 + t;
    float4 acc;
    {
        float4 v = __ldcg(pxb + (size_t)own_c * HW4);
        acc.x = v.x * w_own;
        acc.y = v.y * w_own;
        acc.z = v.z * w_own;
        acc.w = v.w * w_own;
    }

    // ---------------- Barrier WAIT (overlapped by the loads above) ---------
    if (t == 0) {
        const unsigned target = s_target;
        while (*(volatile unsigned*)&g_cnt[b] < target)
            __nanosleep(64);
        __threadfence();                              // acquire before g_w reads
    }
    __syncthreads();
    // Reload all weights; ZERO the own channel (already accumulated) so the
    // main loop is uniform and branch-free.
    if (t < NC) w[t] = (t == own_c) ? 0.0f : __ldcg(&g_w[b * NC + t]);
    __syncthreads();

    // ------- Phase B part 2: uniform branch-free 64-plane sweep ------------
    #pragma unroll 8
    for (int c = 0; c < NC; ++c) {
        float4 v = __ldcs(pxb + (size_t)c * HW4);
        const float wc = w[c];
        acc.x += v.x * wc;
        acc.y += v.y * wc;
        acc.z += v.z * wc;
        acc.w += v.w * wc;
    }

    out4[(size_t)blk * 256 + t] = acc;
}

extern "C" void kernel_launch(void* const* d_in, const int* in_sizes, int n_in,
                              void* d_out, int out_size) {
    const float4* x4 = (const float4*)d_in[0];
    const float4* y4 = (const float4*)d_in[1];
    float4* out4 = (float4*)d_out;

    fused_kernel<<<NB * NC, 256>>>(x4, y4, out4);
}

// round 10
// speedup vs baseline: 1.0105x; 1.0004x over previous
#include <cuda_runtime.h>

// Shapes: x, y : (16, 64, 256, 256) fp32 ; out : (16, 256, 256) fp32
// out[b,i] = sum_c x[b,c,i] * w[b,c],  w[b,c] = sum_j y[b,c,j] / (65536*4194304)
//
// Fused single kernel, 1024 blocks x 256 threads, all resident in one wave
// (launch_bounds(256,7) -> 7 x 148 = 1036 >= 1024 : required, the per-batch
// barrier deadlocks if any block of a batch is non-resident).
//
// Barrier: monotonic per-batch ticket counter (NEVER reset). ticket/64 gives
// the round; wait until counter >= (round+1)*64. Single location, total order
// from atomicAdd, stale reads only under-read -> deadlock-free by construction.
//
// R10: phase B part 2 is a 63-iteration BRANCH-FREE loop with index remap
// c = k + (k >= own_c), skipping the own plane WITHOUT re-reading it
// (saves 4MB of redundant traffic vs the w[own_c]=0 uniform-64 variant)
// and WITHOUT a data-dependent branch (which measurably broke LDG
// front-batching in R1). Addresses stay independently computable per
// unrolled body -> MLP preserved.

#define NB 16
#define NC 64
#define HW 65536               // 256*256
#define HW4 (HW / 4)           // 16384 float4 per (b,c) plane
#define SCALE (1.0f / (65536.0f * 4194304.0f))  // exact: 2^-38

__device__ float g_w[NB * NC];
__device__ unsigned int g_cnt[NB];     // monotonic ticket counter (never reset)

__global__ void __launch_bounds__(256, 7)
fused_kernel(const float4* __restrict__ x4,
             const float4* __restrict__ y4,
             float4* __restrict__ out4) {
    const int blk = blockIdx.x;            // 0..1023 == plane index b*64+c
    const int b = blk >> 6;                // batch
    const int own_c = blk & 63;            // this block's channel / output chunk
    const int t = threadIdx.x;

    __shared__ float w[NC];
    __shared__ float red[8];
    __shared__ unsigned int s_target;

    // ---------------- Phase A: reduce y-plane blk ----------------
    {
        const float4* p = y4 + (size_t)blk * HW4;
        float s = 0.0f;
        #pragma unroll 8
        for (int k = 0; k < 64; ++k) {
            float4 v = __ldcs(&p[t + k * 256]);   // y read exactly once: stream
            s += (v.x + v.y) + (v.z + v.w);
        }
        #pragma unroll
        for (int o = 16; o > 0; o >>= 1)
            s += __shfl_xor_sync(0xFFFFFFFF, s, o);
        if ((t & 31) == 0) red[t >> 5] = s;
    }
    __syncthreads();

    // ------------- Publish w_own + barrier ARRIVE (ticket, no wait) --------
    float w_own = 0.0f;
    if (t == 0) {
        float tot = 0.0f;
        #pragma unroll
        for (int i = 0; i < 8; ++i) tot += red[i];
        const float wo = tot * SCALE;
        g_w[blk] = wo;                                // publish for batch peers
        red[0] = wo;                                  // local broadcast slot
        __threadfence();                              // release g_w[blk]
        unsigned ticket = atomicAdd(&g_cnt[b], 1u);   // totally ordered arrive
        s_target = ((ticket >> 6) + 1u) << 6;         // end of this round
    }
    __syncthreads();
    w_own = red[0];

    // ------- Phase B part 1: own plane pre-accumulation (overlaps wait) ----
    const float4* pxb = x4 + (size_t)b * NC * HW4 + own_c * 256 + t;
    float4 acc;
    {
        float4 v = __ldcs(pxb + (size_t)own_c * HW4); // own plane read ONCE
        acc.x = v.x * w_own;
        acc.y = v.y * w_own;
        acc.z = v.z * w_own;
        acc.w = v.w * w_own;
    }

    // ---------------- Barrier WAIT (overlapped by the loads above) ---------
    if (t == 0) {
        const unsigned target = s_target;
        while (*(volatile unsigned*)&g_cnt[b] < target)
            __nanosleep(64);
        __threadfence();                              // acquire before g_w reads
    }
    __syncthreads();
    if (t < NC) w[t] = __ldcg(&g_w[b * NC + t]);      // L2-coherent reload
    __syncthreads();

    // ------- Phase B part 2: 63 planes, branch-free index remap ------------
    // c = k + (k >= own_c) visits 0..63 except own_c; per-iteration cost is
    // one ISETP+IADD (ALU ~1% busy), addresses independent -> batching kept.
    #pragma unroll 7
    for (int k = 0; k < NC - 1; ++k) {
        const int c = k + (int)(k >= own_c);
        float4 v = __ldcs(pxb + (size_t)c * HW4);     // x read exactly once
        const float wc = w[c];
        acc.x += v.x * wc;
        acc.y += v.y * wc;
        acc.z += v.z * wc;
        acc.w += v.w * wc;
    }

    out4[(size_t)blk * 256 + t] = acc;
}

extern "C" void kernel_launch(void* const* d_in, const int* in_sizes, int n_in,
                              void* d_out, int out_size) {
    const float4* x4 = (const float4*)d_in[0];
    const float4* y4 = (const float4*)d_in[1];
    float4* out4 = (float4*)d_out;

    fused_kernel<<<NB * NC, 256>>>(x4, y4, out4);
}